// round 4
// baseline (speedup 1.0000x reference)
#include <cuda_runtime.h>
#include <cuda_bf16.h>
#include <cstdint>

// Problem dims
#define B_DIM 4096
#define I_DIM 1024
#define O_DIM 1024
#define NDEG  9            // d = 0..8 ; d=0 (V0=2) folded into bias
#define K_DIM (I_DIM * 8)  // 8192 : k = i*8 + (d-1)

// GEMM tiling
#define BM 128
#define BN 128
#define BK 32
#define SA_STRIDE 40   // bf16 elems, padded (128x32 A tile)
#define SB_STRIDE 136  // bf16 elems, padded (32x128 B tile)

// -------- device scratch (no runtime allocation allowed) --------
__device__ __align__(256) __nv_bfloat16 g_Ahi[(size_t)B_DIM * K_DIM];
__device__ __align__(256) __nv_bfloat16 g_Alo[(size_t)B_DIM * K_DIM];
__device__ __align__(256) __nv_bfloat16 g_Whi[(size_t)K_DIM * O_DIM];
__device__ __align__(256) __nv_bfloat16 g_Wlo[(size_t)K_DIM * O_DIM];
__device__ __align__(256) float         g_bias[O_DIM];

union Pack8 { uint4 u; __nv_bfloat16 h[8]; };

// -------- kernel 1: basis = Vieta-Pell(tanh(x)), split into bf16 hi/lo --------
__global__ void vp_basis_kernel(const float* __restrict__ x) {
    int idx = blockIdx.x * blockDim.x + threadIdx.x;  // b*I + i
    if (idx >= B_DIM * I_DIM) return;
    float t = tanhf(x[idx]);
    float v[NDEG];
    v[0] = 2.0f; v[1] = t;
#pragma unroll
    for (int d = 2; d < NDEG; d++) v[d] = t * v[d - 1] + v[d - 2];

    Pack8 hi, lo;
#pragma unroll
    for (int d = 1; d < NDEG; d++) {
        float f = v[d];
        __nv_bfloat16 h = __float2bfloat16(f);
        hi.h[d - 1] = h;
        lo.h[d - 1] = __float2bfloat16(f - __bfloat162float(h));
    }
    size_t base = (size_t)(idx >> 10) * K_DIM + (size_t)(idx & 1023) * 8;
    *reinterpret_cast<uint4*>(g_Ahi + base) = hi.u;
    *reinterpret_cast<uint4*>(g_Alo + base) = lo.u;
}

// -------- kernel 2: W[k=i*8+(d-1)][o] = coeffs[i][o][d], bf16 hi/lo --------
__global__ void vp_wprep_kernel(const float* __restrict__ coeffs) {
    int idx = blockIdx.x * blockDim.x + threadIdx.x;  // i*O + o
    if (idx >= I_DIM * O_DIM) return;
    int i = idx >> 10, o = idx & 1023;
    const float* src = coeffs + (size_t)idx * NDEG;
#pragma unroll
    for (int d = 1; d < NDEG; d++) {
        float f = src[d];
        __nv_bfloat16 h = __float2bfloat16(f);
        size_t w = (size_t)(i * 8 + d - 1) * O_DIM + o;
        g_Whi[w] = h;
        g_Wlo[w] = __float2bfloat16(f - __bfloat162float(h));
    }
}

// -------- kernel 3: bias[o] = 2 * sum_i coeffs[i][o][0] --------
__global__ void vp_bias_kernel(const float* __restrict__ coeffs) {
    __shared__ float red[256];
    int o = blockIdx.x;
    int t = threadIdx.x;
    float s = 0.0f;
#pragma unroll
    for (int j = 0; j < I_DIM / 256; j++) {
        int i = t + j * 256;
        s += coeffs[((size_t)i * O_DIM + o) * NDEG];
    }
    red[t] = s;
    __syncthreads();
    for (int off = 128; off > 0; off >>= 1) {
        if (t < off) red[t] += red[t + off];
        __syncthreads();
    }
    if (t == 0) g_bias[o] = 2.0f * red[0];
}

// -------- mma / ldmatrix helpers --------
__device__ __forceinline__ uint32_t smem_u32(const void* p) {
    return (uint32_t)__cvta_generic_to_shared(p);
}
__device__ __forceinline__ void ldsm_x4(uint32_t* r, uint32_t addr) {
    asm volatile("ldmatrix.sync.aligned.m8n8.x4.shared.b16 {%0,%1,%2,%3}, [%4];"
                 : "=r"(r[0]), "=r"(r[1]), "=r"(r[2]), "=r"(r[3]) : "r"(addr));
}
__device__ __forceinline__ void ldsm_x4_t(uint32_t* r, uint32_t addr) {
    asm volatile("ldmatrix.sync.aligned.m8n8.x4.trans.shared.b16 {%0,%1,%2,%3}, [%4];"
                 : "=r"(r[0]), "=r"(r[1]), "=r"(r[2]), "=r"(r[3]) : "r"(addr));
}
__device__ __forceinline__ void mma16816(float* c, const uint32_t* a, const uint32_t* b) {
    asm volatile(
        "mma.sync.aligned.m16n8k16.row.col.f32.bf16.bf16.f32 "
        "{%0,%1,%2,%3}, {%4,%5,%6,%7}, {%8,%9}, {%0,%1,%2,%3};"
        : "+f"(c[0]), "+f"(c[1]), "+f"(c[2]), "+f"(c[3])
        : "r"(a[0]), "r"(a[1]), "r"(a[2]), "r"(a[3]), "r"(b[0]), "r"(b[1]));
}

// -------- kernel 4: split-bf16 GEMM  out[b][o] = A @ W + bias --------
__global__ __launch_bounds__(256, 1)
void vp_gemm_kernel(float* __restrict__ out) {
    __shared__ __nv_bfloat16 sAhi[BM][SA_STRIDE];
    __shared__ __nv_bfloat16 sAlo[BM][SA_STRIDE];
    __shared__ __nv_bfloat16 sBhi[BK][SB_STRIDE];
    __shared__ __nv_bfloat16 sBlo[BK][SB_STRIDE];

    const int tid  = threadIdx.x;
    const int lane = tid & 31;
    const int wid  = tid >> 5;
    const int warp_m = wid & 1;   // 2 warps along M (64 rows each)
    const int warp_n = wid >> 1;  // 4 warps along N (32 cols each)
    const size_t m0 = (size_t)blockIdx.y * BM;
    const size_t n0 = (size_t)blockIdx.x * BN;

    float acc[4][4][4];
#pragma unroll
    for (int a = 0; a < 4; a++)
#pragma unroll
        for (int b = 0; b < 4; b++)
#pragma unroll
            for (int c = 0; c < 4; c++) acc[a][b][c] = 0.0f;

    // global->smem load coordinates (each thread: 2 x uint4 per matrix)
    const int ra0 = tid >> 2,          ca0 = (tid & 3) * 8;
    const int ra1 = (tid + 256) >> 2,  ca1 = (tid & 3) * 8;     // (tid+256)&3 == tid&3
    const int kb0 = tid >> 4,          nb0 = (tid & 15) * 8;
    const int kb1 = (tid + 256) >> 4,  nb1 = (tid & 15) * 8;

    // ldmatrix lane coordinates
    const int lrow = lane & 15;
    const int lc8  = (lane >> 4) * 8;

    for (int k0 = 0; k0 < K_DIM; k0 += BK) {
        // ---- load A tile (128x32) hi/lo ----
        *reinterpret_cast<uint4*>(&sAhi[ra0][ca0]) =
            *reinterpret_cast<const uint4*>(g_Ahi + (m0 + ra0) * K_DIM + k0 + ca0);
        *reinterpret_cast<uint4*>(&sAhi[ra1][ca1]) =
            *reinterpret_cast<const uint4*>(g_Ahi + (m0 + ra1) * K_DIM + k0 + ca1);
        *reinterpret_cast<uint4*>(&sAlo[ra0][ca0]) =
            *reinterpret_cast<const uint4*>(g_Alo + (m0 + ra0) * K_DIM + k0 + ca0);
        *reinterpret_cast<uint4*>(&sAlo[ra1][ca1]) =
            *reinterpret_cast<const uint4*>(g_Alo + (m0 + ra1) * K_DIM + k0 + ca1);
        // ---- load B tile (32x128) hi/lo ----
        *reinterpret_cast<uint4*>(&sBhi[kb0][nb0]) =
            *reinterpret_cast<const uint4*>(g_Whi + (size_t)(k0 + kb0) * O_DIM + n0 + nb0);
        *reinterpret_cast<uint4*>(&sBhi[kb1][nb1]) =
            *reinterpret_cast<const uint4*>(g_Whi + (size_t)(k0 + kb1) * O_DIM + n0 + nb1);
        *reinterpret_cast<uint4*>(&sBlo[kb0][nb0]) =
            *reinterpret_cast<const uint4*>(g_Wlo + (size_t)(k0 + kb0) * O_DIM + n0 + nb0);
        *reinterpret_cast<uint4*>(&sBlo[kb1][nb1]) =
            *reinterpret_cast<const uint4*>(g_Wlo + (size_t)(k0 + kb1) * O_DIM + n0 + nb1);

        __syncthreads();

#pragma unroll
        for (int ks = 0; ks < BK; ks += 16) {
            uint32_t ah[4][4], al[4][4], bh[4][2], bl[4][2];
#pragma unroll
            for (int mt = 0; mt < 4; mt++) {
                int row = warp_m * 64 + mt * 16 + lrow;
                int col = ks + lc8;
                ldsm_x4(ah[mt], smem_u32(&sAhi[row][col]));
                ldsm_x4(al[mt], smem_u32(&sAlo[row][col]));
            }
#pragma unroll
            for (int np = 0; np < 2; np++) {
                uint32_t t4[4];
                int krow = ks + lrow;
                int ncol = warp_n * 32 + np * 16 + lc8;
                ldsm_x4_t(t4, smem_u32(&sBhi[krow][ncol]));
                bh[np * 2][0] = t4[0]; bh[np * 2][1] = t4[1];
                bh[np * 2 + 1][0] = t4[2]; bh[np * 2 + 1][1] = t4[3];
                ldsm_x4_t(t4, smem_u32(&sBlo[krow][ncol]));
                bl[np * 2][0] = t4[0]; bl[np * 2][1] = t4[1];
                bl[np * 2 + 1][0] = t4[2]; bl[np * 2 + 1][1] = t4[3];
            }
#pragma unroll
            for (int mt = 0; mt < 4; mt++)
#pragma unroll
                for (int nt = 0; nt < 4; nt++) {
                    mma16816(acc[mt][nt], ah[mt], bh[nt]);  // Ah*Wh
                    mma16816(acc[mt][nt], ah[mt], bl[nt]);  // Ah*Wl
                    mma16816(acc[mt][nt], al[mt], bh[nt]);  // Al*Wh
                }
        }
        __syncthreads();
    }

    // ---- epilogue: + bias, write fp32 ----
    const int g   = lane >> 2;
    const int tig = lane & 3;
#pragma unroll
    for (int mt = 0; mt < 4; mt++) {
#pragma unroll
        for (int nt = 0; nt < 4; nt++) {
            int row = (int)m0 + warp_m * 64 + mt * 16 + g;
            int col = (int)n0 + warp_n * 32 + nt * 8 + tig * 2;
            float b0 = g_bias[col], b1 = g_bias[col + 1];
            float2 r0 = make_float2(acc[mt][nt][0] + b0, acc[mt][nt][1] + b1);
            float2 r1 = make_float2(acc[mt][nt][2] + b0, acc[mt][nt][3] + b1);
            *reinterpret_cast<float2*>(&out[(size_t)row * O_DIM + col]) = r0;
            *reinterpret_cast<float2*>(&out[(size_t)(row + 8) * O_DIM + col]) = r1;
        }
    }
}

// -------- launch --------
extern "C" void kernel_launch(void* const* d_in, const int* in_sizes, int n_in,
                              void* d_out, int out_size) {
    const float* x      = (const float*)d_in[0];
    const float* coeffs = (const float*)d_in[1];
    float* out          = (float*)d_out;

    vp_basis_kernel<<<(B_DIM * I_DIM + 255) / 256, 256>>>(x);
    vp_wprep_kernel<<<(I_DIM * O_DIM + 255) / 256, 256>>>(coeffs);
    vp_bias_kernel<<<O_DIM, 256>>>(coeffs);
    vp_gemm_kernel<<<dim3(O_DIM / BN, B_DIM / BM), 256>>>(out);
}

// round 5
// speedup vs baseline: 1.0014x; 1.0014x over previous
#include <cuda_runtime.h>
#include <cuda_bf16.h>
#include <cstdint>

// Problem dims
#define B_DIM 4096
#define I_DIM 1024
#define O_DIM 1024
#define NDEG  9            // d = 0..8 ; d=0 (V0=2) folded into bias
#define K_DIM (I_DIM * 8)  // 8192 : k = i*8 + (d-1)

// GEMM tiling
#define BM 128
#define BN 128
#define BK 32
#define SA_STRIDE 40   // bf16 elems, padded (128x32 A tile)
#define SB_STRIDE 136  // bf16 elems, padded (32x128 B tile)

// -------- device scratch (no runtime allocation allowed) --------
__device__ __align__(256) __nv_bfloat16 g_Ahi[(size_t)B_DIM * K_DIM];
__device__ __align__(256) __nv_bfloat16 g_Alo[(size_t)B_DIM * K_DIM];
__device__ __align__(256) __nv_bfloat16 g_Whi[(size_t)K_DIM * O_DIM];
__device__ __align__(256) __nv_bfloat16 g_Wlo[(size_t)K_DIM * O_DIM];
__device__ __align__(256) float         g_bias[O_DIM];

union Pack8 { uint4 u; __nv_bfloat16 h[8]; };

// -------- kernel 1: basis = Vieta-Pell(tanh(x)), split into bf16 hi/lo --------
__global__ void vp_basis_kernel(const float* __restrict__ x) {
    int idx = blockIdx.x * blockDim.x + threadIdx.x;  // b*I + i
    if (idx >= B_DIM * I_DIM) return;
    float t = tanhf(x[idx]);
    float v[NDEG];
    v[0] = 2.0f; v[1] = t;
#pragma unroll
    for (int d = 2; d < NDEG; d++) v[d] = t * v[d - 1] + v[d - 2];

    Pack8 hi, lo;
#pragma unroll
    for (int d = 1; d < NDEG; d++) {
        float f = v[d];
        __nv_bfloat16 h = __float2bfloat16(f);
        hi.h[d - 1] = h;
        lo.h[d - 1] = __float2bfloat16(f - __bfloat162float(h));
    }
    size_t base = (size_t)(idx >> 10) * K_DIM + (size_t)(idx & 1023) * 8;
    *reinterpret_cast<uint4*>(g_Ahi + base) = hi.u;
    *reinterpret_cast<uint4*>(g_Alo + base) = lo.u;
}

// -------- kernel 2: W[k=i*8+(d-1)][o] = coeffs[i][o][d], bf16 hi/lo --------
__global__ void vp_wprep_kernel(const float* __restrict__ coeffs) {
    int idx = blockIdx.x * blockDim.x + threadIdx.x;  // i*O + o
    if (idx >= I_DIM * O_DIM) return;
    int i = idx >> 10, o = idx & 1023;
    const float* src = coeffs + (size_t)idx * NDEG;
#pragma unroll
    for (int d = 1; d < NDEG; d++) {
        float f = src[d];
        __nv_bfloat16 h = __float2bfloat16(f);
        size_t w = (size_t)(i * 8 + d - 1) * O_DIM + o;
        g_Whi[w] = h;
        g_Wlo[w] = __float2bfloat16(f - __bfloat162float(h));
    }
}

// -------- kernel 3: bias[o] = 2 * sum_i coeffs[i][o][0] --------
__global__ void vp_bias_kernel(const float* __restrict__ coeffs) {
    __shared__ float red[256];
    int o = blockIdx.x;
    int t = threadIdx.x;
    float s = 0.0f;
#pragma unroll
    for (int j = 0; j < I_DIM / 256; j++) {
        int i = t + j * 256;
        s += coeffs[((size_t)i * O_DIM + o) * NDEG];
    }
    red[t] = s;
    __syncthreads();
    for (int off = 128; off > 0; off >>= 1) {
        if (t < off) red[t] += red[t + off];
        __syncthreads();
    }
    if (t == 0) g_bias[o] = 2.0f * red[0];
}

// -------- mma / ldmatrix helpers --------
__device__ __forceinline__ uint32_t smem_u32(const void* p) {
    return (uint32_t)__cvta_generic_to_shared(p);
}
__device__ __forceinline__ void ldsm_x4(uint32_t* r, uint32_t addr) {
    asm volatile("ldmatrix.sync.aligned.m8n8.x4.shared.b16 {%0,%1,%2,%3}, [%4];"
                 : "=r"(r[0]), "=r"(r[1]), "=r"(r[2]), "=r"(r[3]) : "r"(addr));
}
__device__ __forceinline__ void ldsm_x4_t(uint32_t* r, uint32_t addr) {
    asm volatile("ldmatrix.sync.aligned.m8n8.x4.trans.shared.b16 {%0,%1,%2,%3}, [%4];"
                 : "=r"(r[0]), "=r"(r[1]), "=r"(r[2]), "=r"(r[3]) : "r"(addr));
}
__device__ __forceinline__ void mma16816(float* c, const uint32_t* a, const uint32_t* b) {
    asm volatile(
        "mma.sync.aligned.m16n8k16.row.col.f32.bf16.bf16.f32 "
        "{%0,%1,%2,%3}, {%4,%5,%6,%7}, {%8,%9}, {%0,%1,%2,%3};"
        : "+f"(c[0]), "+f"(c[1]), "+f"(c[2]), "+f"(c[3])
        : "r"(a[0]), "r"(a[1]), "r"(a[2]), "r"(a[3]), "r"(b[0]), "r"(b[1]));
}

// -------- kernel 4: split-bf16 GEMM  out[b][o] = A @ W + bias --------
__global__ __launch_bounds__(256, 1)
void vp_gemm_kernel(float* __restrict__ out) {
    __shared__ __nv_bfloat16 sAhi[BM][SA_STRIDE];
    __shared__ __nv_bfloat16 sAlo[BM][SA_STRIDE];
    __shared__ __nv_bfloat16 sBhi[BK][SB_STRIDE];
    __shared__ __nv_bfloat16 sBlo[BK][SB_STRIDE];

    const int tid  = threadIdx.x;
    const int lane = tid & 31;
    const int wid  = tid >> 5;
    const int warp_m = wid & 1;   // 2 warps along M (64 rows each)
    const int warp_n = wid >> 1;  // 4 warps along N (32 cols each)
    const size_t m0 = (size_t)blockIdx.y * BM;
    const size_t n0 = (size_t)blockIdx.x * BN;

    float acc[4][4][4];
#pragma unroll
    for (int a = 0; a < 4; a++)
#pragma unroll
        for (int b = 0; b < 4; b++)
#pragma unroll
            for (int c = 0; c < 4; c++) acc[a][b][c] = 0.0f;

    // global->smem load coordinates (each thread: 2 x uint4 per matrix)
    const int ra0 = tid >> 2,          ca0 = (tid & 3) * 8;
    const int ra1 = (tid + 256) >> 2,  ca1 = (tid & 3) * 8;     // (tid+256)&3 == tid&3
    const int kb0 = tid >> 4,          nb0 = (tid & 15) * 8;
    const int kb1 = (tid + 256) >> 4,  nb1 = (tid & 15) * 8;

    // ldmatrix lane coordinates
    const int lrow = lane & 15;
    const int lc8  = (lane >> 4) * 8;

    for (int k0 = 0; k0 < K_DIM; k0 += BK) {
        // ---- load A tile (128x32) hi/lo ----
        *reinterpret_cast<uint4*>(&sAhi[ra0][ca0]) =
            *reinterpret_cast<const uint4*>(g_Ahi + (m0 + ra0) * K_DIM + k0 + ca0);
        *reinterpret_cast<uint4*>(&sAhi[ra1][ca1]) =
            *reinterpret_cast<const uint4*>(g_Ahi + (m0 + ra1) * K_DIM + k0 + ca1);
        *reinterpret_cast<uint4*>(&sAlo[ra0][ca0]) =
            *reinterpret_cast<const uint4*>(g_Alo + (m0 + ra0) * K_DIM + k0 + ca0);
        *reinterpret_cast<uint4*>(&sAlo[ra1][ca1]) =
            *reinterpret_cast<const uint4*>(g_Alo + (m0 + ra1) * K_DIM + k0 + ca1);
        // ---- load B tile (32x128) hi/lo ----
        *reinterpret_cast<uint4*>(&sBhi[kb0][nb0]) =
            *reinterpret_cast<const uint4*>(g_Whi + (size_t)(k0 + kb0) * O_DIM + n0 + nb0);
        *reinterpret_cast<uint4*>(&sBhi[kb1][nb1]) =
            *reinterpret_cast<const uint4*>(g_Whi + (size_t)(k0 + kb1) * O_DIM + n0 + nb1);
        *reinterpret_cast<uint4*>(&sBlo[kb0][nb0]) =
            *reinterpret_cast<const uint4*>(g_Wlo + (size_t)(k0 + kb0) * O_DIM + n0 + nb0);
        *reinterpret_cast<uint4*>(&sBlo[kb1][nb1]) =
            *reinterpret_cast<const uint4*>(g_Wlo + (size_t)(k0 + kb1) * O_DIM + n0 + nb1);

        __syncthreads();

#pragma unroll
        for (int ks = 0; ks < BK; ks += 16) {
            uint32_t ah[4][4], al[4][4], bh[4][2], bl[4][2];
#pragma unroll
            for (int mt = 0; mt < 4; mt++) {
                int row = warp_m * 64 + mt * 16 + lrow;
                int col = ks + lc8;
                ldsm_x4(ah[mt], smem_u32(&sAhi[row][col]));
                ldsm_x4(al[mt], smem_u32(&sAlo[row][col]));
            }
#pragma unroll
            for (int np = 0; np < 2; np++) {
                uint32_t t4[4];
                int krow = ks + lrow;
                int ncol = warp_n * 32 + np * 16 + lc8;
                ldsm_x4_t(t4, smem_u32(&sBhi[krow][ncol]));
                bh[np * 2][0] = t4[0]; bh[np * 2][1] = t4[1];
                bh[np * 2 + 1][0] = t4[2]; bh[np * 2 + 1][1] = t4[3];
                ldsm_x4_t(t4, smem_u32(&sBlo[krow][ncol]));
                bl[np * 2][0] = t4[0]; bl[np * 2][1] = t4[1];
                bl[np * 2 + 1][0] = t4[2]; bl[np * 2 + 1][1] = t4[3];
            }
#pragma unroll
            for (int mt = 0; mt < 4; mt++)
#pragma unroll
                for (int nt = 0; nt < 4; nt++) {
                    mma16816(acc[mt][nt], ah[mt], bh[nt]);  // Ah*Wh
                    mma16816(acc[mt][nt], ah[mt], bl[nt]);  // Ah*Wl
                    mma16816(acc[mt][nt], al[mt], bh[nt]);  // Al*Wh
                }
        }
        __syncthreads();
    }

    // ---- epilogue: + bias, write fp32 ----
    const int g   = lane >> 2;
    const int tig = lane & 3;
#pragma unroll
    for (int mt = 0; mt < 4; mt++) {
#pragma unroll
        for (int nt = 0; nt < 4; nt++) {
            int row = (int)m0 + warp_m * 64 + mt * 16 + g;
            int col = (int)n0 + warp_n * 32 + nt * 8 + tig * 2;
            float b0 = g_bias[col], b1 = g_bias[col + 1];
            float2 r0 = make_float2(acc[mt][nt][0] + b0, acc[mt][nt][1] + b1);
            float2 r1 = make_float2(acc[mt][nt][2] + b0, acc[mt][nt][3] + b1);
            *reinterpret_cast<float2*>(&out[(size_t)row * O_DIM + col]) = r0;
            *reinterpret_cast<float2*>(&out[(size_t)(row + 8) * O_DIM + col]) = r1;
        }
    }
}

// -------- launch --------
extern "C" void kernel_launch(void* const* d_in, const int* in_sizes, int n_in,
                              void* d_out, int out_size) {
    const float* x      = (const float*)d_in[0];
    const float* coeffs = (const float*)d_in[1];
    float* out          = (float*)d_out;

    vp_basis_kernel<<<(B_DIM * I_DIM + 255) / 256, 256>>>(x);
    vp_wprep_kernel<<<(I_DIM * O_DIM + 255) / 256, 256>>>(coeffs);
    vp_bias_kernel<<<O_DIM, 256>>>(coeffs);
    vp_gemm_kernel<<<dim3(O_DIM / BN, B_DIM / BM), 256>>>(out);
}

// round 6
// speedup vs baseline: 1.0030x; 1.0016x over previous
#include <cuda_runtime.h>
#include <cuda_bf16.h>
#include <cstdint>

// Problem dims
#define B_DIM 4096
#define I_DIM 1024
#define O_DIM 1024
#define NDEG  9            // d = 0..8 ; d=0 (V0=2) folded into bias
#define K_DIM (I_DIM * 8)  // 8192 : k = i*8 + (d-1)

// GEMM tiling
#define BM 128
#define BN 128
#define BK 32
#define SA_STRIDE 40   // bf16 elems, padded (128x32 A tile)
#define SB_STRIDE 136  // bf16 elems, padded (32x128 B tile)

// -------- device scratch (no runtime allocation allowed) --------
__device__ __align__(256) __nv_bfloat16 g_Ahi[(size_t)B_DIM * K_DIM];
__device__ __align__(256) __nv_bfloat16 g_Alo[(size_t)B_DIM * K_DIM];
__device__ __align__(256) __nv_bfloat16 g_Whi[(size_t)K_DIM * O_DIM];
__device__ __align__(256) __nv_bfloat16 g_Wlo[(size_t)K_DIM * O_DIM];
__device__ __align__(256) float         g_bias[O_DIM];

union Pack8 { uint4 u; __nv_bfloat16 h[8]; };

// -------- kernel 1: basis = Vieta-Pell(tanh(x)), split into bf16 hi/lo --------
__global__ void vp_basis_kernel(const float* __restrict__ x) {
    int idx = blockIdx.x * blockDim.x + threadIdx.x;  // b*I + i
    if (idx >= B_DIM * I_DIM) return;
    float t = tanhf(x[idx]);
    float v[NDEG];
    v[0] = 2.0f; v[1] = t;
#pragma unroll
    for (int d = 2; d < NDEG; d++) v[d] = t * v[d - 1] + v[d - 2];

    Pack8 hi, lo;
#pragma unroll
    for (int d = 1; d < NDEG; d++) {
        float f = v[d];
        __nv_bfloat16 h = __float2bfloat16(f);
        hi.h[d - 1] = h;
        lo.h[d - 1] = __float2bfloat16(f - __bfloat162float(h));
    }
    size_t base = (size_t)(idx >> 10) * K_DIM + (size_t)(idx & 1023) * 8;
    *reinterpret_cast<uint4*>(g_Ahi + base) = hi.u;
    *reinterpret_cast<uint4*>(g_Alo + base) = lo.u;
}

// -------- kernel 2: W[k=i*8+(d-1)][o] = coeffs[i][o][d], bf16 hi/lo --------
__global__ void vp_wprep_kernel(const float* __restrict__ coeffs) {
    int idx = blockIdx.x * blockDim.x + threadIdx.x;  // i*O + o
    if (idx >= I_DIM * O_DIM) return;
    int i = idx >> 10, o = idx & 1023;
    const float* src = coeffs + (size_t)idx * NDEG;
#pragma unroll
    for (int d = 1; d < NDEG; d++) {
        float f = src[d];
        __nv_bfloat16 h = __float2bfloat16(f);
        size_t w = (size_t)(i * 8 + d - 1) * O_DIM + o;
        g_Whi[w] = h;
        g_Wlo[w] = __float2bfloat16(f - __bfloat162float(h));
    }
}

// -------- kernel 3: bias[o] = 2 * sum_i coeffs[i][o][0] --------
__global__ void vp_bias_kernel(const float* __restrict__ coeffs) {
    __shared__ float red[256];
    int o = blockIdx.x;
    int t = threadIdx.x;
    float s = 0.0f;
#pragma unroll
    for (int j = 0; j < I_DIM / 256; j++) {
        int i = t + j * 256;
        s += coeffs[((size_t)i * O_DIM + o) * NDEG];
    }
    red[t] = s;
    __syncthreads();
    for (int off = 128; off > 0; off >>= 1) {
        if (t < off) red[t] += red[t + off];
        __syncthreads();
    }
    if (t == 0) g_bias[o] = 2.0f * red[0];
}

// -------- mma / ldmatrix helpers --------
__device__ __forceinline__ uint32_t smem_u32(const void* p) {
    return (uint32_t)__cvta_generic_to_shared(p);
}
__device__ __forceinline__ void ldsm_x4(uint32_t* r, uint32_t addr) {
    asm volatile("ldmatrix.sync.aligned.m8n8.x4.shared.b16 {%0,%1,%2,%3}, [%4];"
                 : "=r"(r[0]), "=r"(r[1]), "=r"(r[2]), "=r"(r[3]) : "r"(addr));
}
__device__ __forceinline__ void ldsm_x4_t(uint32_t* r, uint32_t addr) {
    asm volatile("ldmatrix.sync.aligned.m8n8.x4.trans.shared.b16 {%0,%1,%2,%3}, [%4];"
                 : "=r"(r[0]), "=r"(r[1]), "=r"(r[2]), "=r"(r[3]) : "r"(addr));
}
__device__ __forceinline__ void mma16816(float* c, const uint32_t* a, const uint32_t* b) {
    asm volatile(
        "mma.sync.aligned.m16n8k16.row.col.f32.bf16.bf16.f32 "
        "{%0,%1,%2,%3}, {%4,%5,%6,%7}, {%8,%9}, {%0,%1,%2,%3};"
        : "+f"(c[0]), "+f"(c[1]), "+f"(c[2]), "+f"(c[3])
        : "r"(a[0]), "r"(a[1]), "r"(a[2]), "r"(a[3]), "r"(b[0]), "r"(b[1]));
}

// -------- kernel 4: split-bf16 GEMM  out[b][o] = A @ W + bias --------
__global__ __launch_bounds__(256, 1)
void vp_gemm_kernel(float* __restrict__ out) {
    __shared__ __nv_bfloat16 sAhi[BM][SA_STRIDE];
    __shared__ __nv_bfloat16 sAlo[BM][SA_STRIDE];
    __shared__ __nv_bfloat16 sBhi[BK][SB_STRIDE];
    __shared__ __nv_bfloat16 sBlo[BK][SB_STRIDE];

    const int tid  = threadIdx.x;
    const int lane = tid & 31;
    const int wid  = tid >> 5;
    const int warp_m = wid & 1;   // 2 warps along M (64 rows each)
    const int warp_n = wid >> 1;  // 4 warps along N (32 cols each)
    const size_t m0 = (size_t)blockIdx.y * BM;
    const size_t n0 = (size_t)blockIdx.x * BN;

    float acc[4][4][4];
#pragma unroll
    for (int a = 0; a < 4; a++)
#pragma unroll
        for (int b = 0; b < 4; b++)
#pragma unroll
            for (int c = 0; c < 4; c++) acc[a][b][c] = 0.0f;

    // global->smem load coordinates (each thread: 2 x uint4 per matrix)
    const int ra0 = tid >> 2,          ca0 = (tid & 3) * 8;
    const int ra1 = (tid + 256) >> 2,  ca1 = (tid & 3) * 8;     // (tid+256)&3 == tid&3
    const int kb0 = tid >> 4,          nb0 = (tid & 15) * 8;
    const int kb1 = (tid + 256) >> 4,  nb1 = (tid & 15) * 8;

    // ldmatrix lane coordinates
    const int lrow = lane & 15;
    const int lc8  = (lane >> 4) * 8;

    for (int k0 = 0; k0 < K_DIM; k0 += BK) {
        // ---- load A tile (128x32) hi/lo ----
        *reinterpret_cast<uint4*>(&sAhi[ra0][ca0]) =
            *reinterpret_cast<const uint4*>(g_Ahi + (m0 + ra0) * K_DIM + k0 + ca0);
        *reinterpret_cast<uint4*>(&sAhi[ra1][ca1]) =
            *reinterpret_cast<const uint4*>(g_Ahi + (m0 + ra1) * K_DIM + k0 + ca1);
        *reinterpret_cast<uint4*>(&sAlo[ra0][ca0]) =
            *reinterpret_cast<const uint4*>(g_Alo + (m0 + ra0) * K_DIM + k0 + ca0);
        *reinterpret_cast<uint4*>(&sAlo[ra1][ca1]) =
            *reinterpret_cast<const uint4*>(g_Alo + (m0 + ra1) * K_DIM + k0 + ca1);
        // ---- load B tile (32x128) hi/lo ----
        *reinterpret_cast<uint4*>(&sBhi[kb0][nb0]) =
            *reinterpret_cast<const uint4*>(g_Whi + (size_t)(k0 + kb0) * O_DIM + n0 + nb0);
        *reinterpret_cast<uint4*>(&sBhi[kb1][nb1]) =
            *reinterpret_cast<const uint4*>(g_Whi + (size_t)(k0 + kb1) * O_DIM + n0 + nb1);
        *reinterpret_cast<uint4*>(&sBlo[kb0][nb0]) =
            *reinterpret_cast<const uint4*>(g_Wlo + (size_t)(k0 + kb0) * O_DIM + n0 + nb0);
        *reinterpret_cast<uint4*>(&sBlo[kb1][nb1]) =
            *reinterpret_cast<const uint4*>(g_Wlo + (size_t)(k0 + kb1) * O_DIM + n0 + nb1);

        __syncthreads();

#pragma unroll
        for (int ks = 0; ks < BK; ks += 16) {
            uint32_t ah[4][4], al[4][4], bh[4][2], bl[4][2];
#pragma unroll
            for (int mt = 0; mt < 4; mt++) {
                int row = warp_m * 64 + mt * 16 + lrow;
                int col = ks + lc8;
                ldsm_x4(ah[mt], smem_u32(&sAhi[row][col]));
                ldsm_x4(al[mt], smem_u32(&sAlo[row][col]));
            }
#pragma unroll
            for (int np = 0; np < 2; np++) {
                uint32_t t4[4];
                int krow = ks + lrow;
                int ncol = warp_n * 32 + np * 16 + lc8;
                ldsm_x4_t(t4, smem_u32(&sBhi[krow][ncol]));
                bh[np * 2][0] = t4[0]; bh[np * 2][1] = t4[1];
                bh[np * 2 + 1][0] = t4[2]; bh[np * 2 + 1][1] = t4[3];
                ldsm_x4_t(t4, smem_u32(&sBlo[krow][ncol]));
                bl[np * 2][0] = t4[0]; bl[np * 2][1] = t4[1];
                bl[np * 2 + 1][0] = t4[2]; bl[np * 2 + 1][1] = t4[3];
            }
#pragma unroll
            for (int mt = 0; mt < 4; mt++)
#pragma unroll
                for (int nt = 0; nt < 4; nt++) {
                    mma16816(acc[mt][nt], ah[mt], bh[nt]);  // Ah*Wh
                    mma16816(acc[mt][nt], ah[mt], bl[nt]);  // Ah*Wl
                    mma16816(acc[mt][nt], al[mt], bh[nt]);  // Al*Wh
                }
        }
        __syncthreads();
    }

    // ---- epilogue: + bias, write fp32 ----
    const int g   = lane >> 2;
    const int tig = lane & 3;
#pragma unroll
    for (int mt = 0; mt < 4; mt++) {
#pragma unroll
        for (int nt = 0; nt < 4; nt++) {
            int row = (int)m0 + warp_m * 64 + mt * 16 + g;
            int col = (int)n0 + warp_n * 32 + nt * 8 + tig * 2;
            float b0 = g_bias[col], b1 = g_bias[col + 1];
            float2 r0 = make_float2(acc[mt][nt][0] + b0, acc[mt][nt][1] + b1);
            float2 r1 = make_float2(acc[mt][nt][2] + b0, acc[mt][nt][3] + b1);
            *reinterpret_cast<float2*>(&out[(size_t)row * O_DIM + col]) = r0;
            *reinterpret_cast<float2*>(&out[(size_t)(row + 8) * O_DIM + col]) = r1;
        }
    }
}

// -------- launch --------
extern "C" void kernel_launch(void* const* d_in, const int* in_sizes, int n_in,
                              void* d_out, int out_size) {
    const float* x      = (const float*)d_in[0];
    const float* coeffs = (const float*)d_in[1];
    float* out          = (float*)d_out;

    vp_basis_kernel<<<(B_DIM * I_DIM + 255) / 256, 256>>>(x);
    vp_wprep_kernel<<<(I_DIM * O_DIM + 255) / 256, 256>>>(coeffs);
    vp_bias_kernel<<<O_DIM, 256>>>(coeffs);
    vp_gemm_kernel<<<dim3(O_DIM / BN, B_DIM / BM), 256>>>(out);
}

// round 7
// speedup vs baseline: 1.0038x; 1.0008x over previous
#include <cuda_runtime.h>
#include <cuda_bf16.h>
#include <cstdint>

// Problem dims
#define B_DIM 4096
#define I_DIM 1024
#define O_DIM 1024
#define NDEG  9            // d = 0..8 ; d=0 (V0=2) folded into bias
#define K_DIM (I_DIM * 8)  // 8192 : k = i*8 + (d-1)

// GEMM tiling
#define BM 128
#define BN 128
#define BK 32
#define SA_STRIDE 40   // bf16 elems, padded (128x32 A tile)
#define SB_STRIDE 136  // bf16 elems, padded (32x128 B tile)

// -------- device scratch (no runtime allocation allowed) --------
__device__ __align__(256) __nv_bfloat16 g_Ahi[(size_t)B_DIM * K_DIM];
__device__ __align__(256) __nv_bfloat16 g_Alo[(size_t)B_DIM * K_DIM];
__device__ __align__(256) __nv_bfloat16 g_Whi[(size_t)K_DIM * O_DIM];
__device__ __align__(256) __nv_bfloat16 g_Wlo[(size_t)K_DIM * O_DIM];
__device__ __align__(256) float         g_bias[O_DIM];

union Pack8 { uint4 u; __nv_bfloat16 h[8]; };

// -------- kernel 1: basis = Vieta-Pell(tanh(x)), split into bf16 hi/lo --------
__global__ void vp_basis_kernel(const float* __restrict__ x) {
    int idx = blockIdx.x * blockDim.x + threadIdx.x;  // b*I + i
    if (idx >= B_DIM * I_DIM) return;
    float t = tanhf(x[idx]);
    float v[NDEG];
    v[0] = 2.0f; v[1] = t;
#pragma unroll
    for (int d = 2; d < NDEG; d++) v[d] = t * v[d - 1] + v[d - 2];

    Pack8 hi, lo;
#pragma unroll
    for (int d = 1; d < NDEG; d++) {
        float f = v[d];
        __nv_bfloat16 h = __float2bfloat16(f);
        hi.h[d - 1] = h;
        lo.h[d - 1] = __float2bfloat16(f - __bfloat162float(h));
    }
    size_t base = (size_t)(idx >> 10) * K_DIM + (size_t)(idx & 1023) * 8;
    *reinterpret_cast<uint4*>(g_Ahi + base) = hi.u;
    *reinterpret_cast<uint4*>(g_Alo + base) = lo.u;
}

// -------- kernel 2: W[k=i*8+(d-1)][o] = coeffs[i][o][d], bf16 hi/lo --------
__global__ void vp_wprep_kernel(const float* __restrict__ coeffs) {
    int idx = blockIdx.x * blockDim.x + threadIdx.x;  // i*O + o
    if (idx >= I_DIM * O_DIM) return;
    int i = idx >> 10, o = idx & 1023;
    const float* src = coeffs + (size_t)idx * NDEG;
#pragma unroll
    for (int d = 1; d < NDEG; d++) {
        float f = src[d];
        __nv_bfloat16 h = __float2bfloat16(f);
        size_t w = (size_t)(i * 8 + d - 1) * O_DIM + o;
        g_Whi[w] = h;
        g_Wlo[w] = __float2bfloat16(f - __bfloat162float(h));
    }
}

// -------- kernel 3: bias[o] = 2 * sum_i coeffs[i][o][0] --------
__global__ void vp_bias_kernel(const float* __restrict__ coeffs) {
    __shared__ float red[256];
    int o = blockIdx.x;
    int t = threadIdx.x;
    float s = 0.0f;
#pragma unroll
    for (int j = 0; j < I_DIM / 256; j++) {
        int i = t + j * 256;
        s += coeffs[((size_t)i * O_DIM + o) * NDEG];
    }
    red[t] = s;
    __syncthreads();
    for (int off = 128; off > 0; off >>= 1) {
        if (t < off) red[t] += red[t + off];
        __syncthreads();
    }
    if (t == 0) g_bias[o] = 2.0f * red[0];
}

// -------- mma / ldmatrix helpers --------
__device__ __forceinline__ uint32_t smem_u32(const void* p) {
    return (uint32_t)__cvta_generic_to_shared(p);
}
__device__ __forceinline__ void ldsm_x4(uint32_t* r, uint32_t addr) {
    asm volatile("ldmatrix.sync.aligned.m8n8.x4.shared.b16 {%0,%1,%2,%3}, [%4];"
                 : "=r"(r[0]), "=r"(r[1]), "=r"(r[2]), "=r"(r[3]) : "r"(addr));
}
__device__ __forceinline__ void ldsm_x4_t(uint32_t* r, uint32_t addr) {
    asm volatile("ldmatrix.sync.aligned.m8n8.x4.trans.shared.b16 {%0,%1,%2,%3}, [%4];"
                 : "=r"(r[0]), "=r"(r[1]), "=r"(r[2]), "=r"(r[3]) : "r"(addr));
}
__device__ __forceinline__ void mma16816(float* c, const uint32_t* a, const uint32_t* b) {
    asm volatile(
        "mma.sync.aligned.m16n8k16.row.col.f32.bf16.bf16.f32 "
        "{%0,%1,%2,%3}, {%4,%5,%6,%7}, {%8,%9}, {%0,%1,%2,%3};"
        : "+f"(c[0]), "+f"(c[1]), "+f"(c[2]), "+f"(c[3])
        : "r"(a[0]), "r"(a[1]), "r"(a[2]), "r"(a[3]), "r"(b[0]), "r"(b[1]));
}

// -------- kernel 4: split-bf16 GEMM  out[b][o] = A @ W + bias --------
__global__ __launch_bounds__(256, 1)
void vp_gemm_kernel(float* __restrict__ out) {
    __shared__ __nv_bfloat16 sAhi[BM][SA_STRIDE];
    __shared__ __nv_bfloat16 sAlo[BM][SA_STRIDE];
    __shared__ __nv_bfloat16 sBhi[BK][SB_STRIDE];
    __shared__ __nv_bfloat16 sBlo[BK][SB_STRIDE];

    const int tid  = threadIdx.x;
    const int lane = tid & 31;
    const int wid  = tid >> 5;
    const int warp_m = wid & 1;   // 2 warps along M (64 rows each)
    const int warp_n = wid >> 1;  // 4 warps along N (32 cols each)
    const size_t m0 = (size_t)blockIdx.y * BM;
    const size_t n0 = (size_t)blockIdx.x * BN;

    float acc[4][4][4];
#pragma unroll
    for (int a = 0; a < 4; a++)
#pragma unroll
        for (int b = 0; b < 4; b++)
#pragma unroll
            for (int c = 0; c < 4; c++) acc[a][b][c] = 0.0f;

    // global->smem load coordinates (each thread: 2 x uint4 per matrix)
    const int ra0 = tid >> 2,          ca0 = (tid & 3) * 8;
    const int ra1 = (tid + 256) >> 2,  ca1 = (tid & 3) * 8;     // (tid+256)&3 == tid&3
    const int kb0 = tid >> 4,          nb0 = (tid & 15) * 8;
    const int kb1 = (tid + 256) >> 4,  nb1 = (tid & 15) * 8;

    // ldmatrix lane coordinates
    const int lrow = lane & 15;
    const int lc8  = (lane >> 4) * 8;

    for (int k0 = 0; k0 < K_DIM; k0 += BK) {
        // ---- load A tile (128x32) hi/lo ----
        *reinterpret_cast<uint4*>(&sAhi[ra0][ca0]) =
            *reinterpret_cast<const uint4*>(g_Ahi + (m0 + ra0) * K_DIM + k0 + ca0);
        *reinterpret_cast<uint4*>(&sAhi[ra1][ca1]) =
            *reinterpret_cast<const uint4*>(g_Ahi + (m0 + ra1) * K_DIM + k0 + ca1);
        *reinterpret_cast<uint4*>(&sAlo[ra0][ca0]) =
            *reinterpret_cast<const uint4*>(g_Alo + (m0 + ra0) * K_DIM + k0 + ca0);
        *reinterpret_cast<uint4*>(&sAlo[ra1][ca1]) =
            *reinterpret_cast<const uint4*>(g_Alo + (m0 + ra1) * K_DIM + k0 + ca1);
        // ---- load B tile (32x128) hi/lo ----
        *reinterpret_cast<uint4*>(&sBhi[kb0][nb0]) =
            *reinterpret_cast<const uint4*>(g_Whi + (size_t)(k0 + kb0) * O_DIM + n0 + nb0);
        *reinterpret_cast<uint4*>(&sBhi[kb1][nb1]) =
            *reinterpret_cast<const uint4*>(g_Whi + (size_t)(k0 + kb1) * O_DIM + n0 + nb1);
        *reinterpret_cast<uint4*>(&sBlo[kb0][nb0]) =
            *reinterpret_cast<const uint4*>(g_Wlo + (size_t)(k0 + kb0) * O_DIM + n0 + nb0);
        *reinterpret_cast<uint4*>(&sBlo[kb1][nb1]) =
            *reinterpret_cast<const uint4*>(g_Wlo + (size_t)(k0 + kb1) * O_DIM + n0 + nb1);

        __syncthreads();

#pragma unroll
        for (int ks = 0; ks < BK; ks += 16) {
            uint32_t ah[4][4], al[4][4], bh[4][2], bl[4][2];
#pragma unroll
            for (int mt = 0; mt < 4; mt++) {
                int row = warp_m * 64 + mt * 16 + lrow;
                int col = ks + lc8;
                ldsm_x4(ah[mt], smem_u32(&sAhi[row][col]));
                ldsm_x4(al[mt], smem_u32(&sAlo[row][col]));
            }
#pragma unroll
            for (int np = 0; np < 2; np++) {
                uint32_t t4[4];
                int krow = ks + lrow;
                int ncol = warp_n * 32 + np * 16 + lc8;
                ldsm_x4_t(t4, smem_u32(&sBhi[krow][ncol]));
                bh[np * 2][0] = t4[0]; bh[np * 2][1] = t4[1];
                bh[np * 2 + 1][0] = t4[2]; bh[np * 2 + 1][1] = t4[3];
                ldsm_x4_t(t4, smem_u32(&sBlo[krow][ncol]));
                bl[np * 2][0] = t4[0]; bl[np * 2][1] = t4[1];
                bl[np * 2 + 1][0] = t4[2]; bl[np * 2 + 1][1] = t4[3];
            }
#pragma unroll
            for (int mt = 0; mt < 4; mt++)
#pragma unroll
                for (int nt = 0; nt < 4; nt++) {
                    mma16816(acc[mt][nt], ah[mt], bh[nt]);  // Ah*Wh
                    mma16816(acc[mt][nt], ah[mt], bl[nt]);  // Ah*Wl
                    mma16816(acc[mt][nt], al[mt], bh[nt]);  // Al*Wh
                }
        }
        __syncthreads();
    }

    // ---- epilogue: + bias, write fp32 ----
    const int g   = lane >> 2;
    const int tig = lane & 3;
#pragma unroll
    for (int mt = 0; mt < 4; mt++) {
#pragma unroll
        for (int nt = 0; nt < 4; nt++) {
            int row = (int)m0 + warp_m * 64 + mt * 16 + g;
            int col = (int)n0 + warp_n * 32 + nt * 8 + tig * 2;
            float b0 = g_bias[col], b1 = g_bias[col + 1];
            float2 r0 = make_float2(acc[mt][nt][0] + b0, acc[mt][nt][1] + b1);
            float2 r1 = make_float2(acc[mt][nt][2] + b0, acc[mt][nt][3] + b1);
            *reinterpret_cast<float2*>(&out[(size_t)row * O_DIM + col]) = r0;
            *reinterpret_cast<float2*>(&out[(size_t)(row + 8) * O_DIM + col]) = r1;
        }
    }
}

// -------- launch --------
extern "C" void kernel_launch(void* const* d_in, const int* in_sizes, int n_in,
                              void* d_out, int out_size) {
    const float* x      = (const float*)d_in[0];
    const float* coeffs = (const float*)d_in[1];
    float* out          = (float*)d_out;

    vp_basis_kernel<<<(B_DIM * I_DIM + 255) / 256, 256>>>(x);
    vp_wprep_kernel<<<(I_DIM * O_DIM + 255) / 256, 256>>>(coeffs);
    vp_bias_kernel<<<O_DIM, 256>>>(coeffs);
    vp_gemm_kernel<<<dim3(O_DIM / BN, B_DIM / BM), 256>>>(out);
}

// round 8
// speedup vs baseline: 1.0041x; 1.0003x over previous
#include <cuda_runtime.h>
#include <cuda_bf16.h>
#include <cstdint>

// Problem dims
#define B_DIM 4096
#define I_DIM 1024
#define O_DIM 1024
#define NDEG  9            // d = 0..8 ; d=0 (V0=2) folded into bias
#define K_DIM (I_DIM * 8)  // 8192 : k = i*8 + (d-1)

// GEMM tiling
#define BM 128
#define BN 128
#define BK 32
#define SA_STRIDE 40   // bf16 elems, padded (128x32 A tile)
#define SB_STRIDE 136  // bf16 elems, padded (32x128 B tile)

// -------- device scratch (no runtime allocation allowed) --------
__device__ __align__(256) __nv_bfloat16 g_Ahi[(size_t)B_DIM * K_DIM];
__device__ __align__(256) __nv_bfloat16 g_Alo[(size_t)B_DIM * K_DIM];
__device__ __align__(256) __nv_bfloat16 g_Whi[(size_t)K_DIM * O_DIM];
__device__ __align__(256) __nv_bfloat16 g_Wlo[(size_t)K_DIM * O_DIM];
__device__ __align__(256) float         g_bias[O_DIM];

union Pack8 { uint4 u; __nv_bfloat16 h[8]; };

// -------- kernel 1: basis = Vieta-Pell(tanh(x)), split into bf16 hi/lo --------
__global__ void vp_basis_kernel(const float* __restrict__ x) {
    int idx = blockIdx.x * blockDim.x + threadIdx.x;  // b*I + i
    if (idx >= B_DIM * I_DIM) return;
    float t = tanhf(x[idx]);
    float v[NDEG];
    v[0] = 2.0f; v[1] = t;
#pragma unroll
    for (int d = 2; d < NDEG; d++) v[d] = t * v[d - 1] + v[d - 2];

    Pack8 hi, lo;
#pragma unroll
    for (int d = 1; d < NDEG; d++) {
        float f = v[d];
        __nv_bfloat16 h = __float2bfloat16(f);
        hi.h[d - 1] = h;
        lo.h[d - 1] = __float2bfloat16(f - __bfloat162float(h));
    }
    size_t base = (size_t)(idx >> 10) * K_DIM + (size_t)(idx & 1023) * 8;
    *reinterpret_cast<uint4*>(g_Ahi + base) = hi.u;
    *reinterpret_cast<uint4*>(g_Alo + base) = lo.u;
}

// -------- kernel 2: W[k=i*8+(d-1)][o] = coeffs[i][o][d], bf16 hi/lo --------
__global__ void vp_wprep_kernel(const float* __restrict__ coeffs) {
    int idx = blockIdx.x * blockDim.x + threadIdx.x;  // i*O + o
    if (idx >= I_DIM * O_DIM) return;
    int i = idx >> 10, o = idx & 1023;
    const float* src = coeffs + (size_t)idx * NDEG;
#pragma unroll
    for (int d = 1; d < NDEG; d++) {
        float f = src[d];
        __nv_bfloat16 h = __float2bfloat16(f);
        size_t w = (size_t)(i * 8 + d - 1) * O_DIM + o;
        g_Whi[w] = h;
        g_Wlo[w] = __float2bfloat16(f - __bfloat162float(h));
    }
}

// -------- kernel 3: bias[o] = 2 * sum_i coeffs[i][o][0] --------
__global__ void vp_bias_kernel(const float* __restrict__ coeffs) {
    __shared__ float red[256];
    int o = blockIdx.x;
    int t = threadIdx.x;
    float s = 0.0f;
#pragma unroll
    for (int j = 0; j < I_DIM / 256; j++) {
        int i = t + j * 256;
        s += coeffs[((size_t)i * O_DIM + o) * NDEG];
    }
    red[t] = s;
    __syncthreads();
    for (int off = 128; off > 0; off >>= 1) {
        if (t < off) red[t] += red[t + off];
        __syncthreads();
    }
    if (t == 0) g_bias[o] = 2.0f * red[0];
}

// -------- mma / ldmatrix helpers --------
__device__ __forceinline__ uint32_t smem_u32(const void* p) {
    return (uint32_t)__cvta_generic_to_shared(p);
}
__device__ __forceinline__ void ldsm_x4(uint32_t* r, uint32_t addr) {
    asm volatile("ldmatrix.sync.aligned.m8n8.x4.shared.b16 {%0,%1,%2,%3}, [%4];"
                 : "=r"(r[0]), "=r"(r[1]), "=r"(r[2]), "=r"(r[3]) : "r"(addr));
}
__device__ __forceinline__ void ldsm_x4_t(uint32_t* r, uint32_t addr) {
    asm volatile("ldmatrix.sync.aligned.m8n8.x4.trans.shared.b16 {%0,%1,%2,%3}, [%4];"
                 : "=r"(r[0]), "=r"(r[1]), "=r"(r[2]), "=r"(r[3]) : "r"(addr));
}
__device__ __forceinline__ void mma16816(float* c, const uint32_t* a, const uint32_t* b) {
    asm volatile(
        "mma.sync.aligned.m16n8k16.row.col.f32.bf16.bf16.f32 "
        "{%0,%1,%2,%3}, {%4,%5,%6,%7}, {%8,%9}, {%0,%1,%2,%3};"
        : "+f"(c[0]), "+f"(c[1]), "+f"(c[2]), "+f"(c[3])
        : "r"(a[0]), "r"(a[1]), "r"(a[2]), "r"(a[3]), "r"(b[0]), "r"(b[1]));
}

// -------- kernel 4: split-bf16 GEMM  out[b][o] = A @ W + bias --------
__global__ __launch_bounds__(256, 1)
void vp_gemm_kernel(float* __restrict__ out) {
    __shared__ __nv_bfloat16 sAhi[BM][SA_STRIDE];
    __shared__ __nv_bfloat16 sAlo[BM][SA_STRIDE];
    __shared__ __nv_bfloat16 sBhi[BK][SB_STRIDE];
    __shared__ __nv_bfloat16 sBlo[BK][SB_STRIDE];

    const int tid  = threadIdx.x;
    const int lane = tid & 31;
    const int wid  = tid >> 5;
    const int warp_m = wid & 1;   // 2 warps along M (64 rows each)
    const int warp_n = wid >> 1;  // 4 warps along N (32 cols each)
    const size_t m0 = (size_t)blockIdx.y * BM;
    const size_t n0 = (size_t)blockIdx.x * BN;

    float acc[4][4][4];
#pragma unroll
    for (int a = 0; a < 4; a++)
#pragma unroll
        for (int b = 0; b < 4; b++)
#pragma unroll
            for (int c = 0; c < 4; c++) acc[a][b][c] = 0.0f;

    // global->smem load coordinates (each thread: 2 x uint4 per matrix)
    const int ra0 = tid >> 2,          ca0 = (tid & 3) * 8;
    const int ra1 = (tid + 256) >> 2,  ca1 = (tid & 3) * 8;     // (tid+256)&3 == tid&3
    const int kb0 = tid >> 4,          nb0 = (tid & 15) * 8;
    const int kb1 = (tid + 256) >> 4,  nb1 = (tid & 15) * 8;

    // ldmatrix lane coordinates
    const int lrow = lane & 15;
    const int lc8  = (lane >> 4) * 8;

    for (int k0 = 0; k0 < K_DIM; k0 += BK) {
        // ---- load A tile (128x32) hi/lo ----
        *reinterpret_cast<uint4*>(&sAhi[ra0][ca0]) =
            *reinterpret_cast<const uint4*>(g_Ahi + (m0 + ra0) * K_DIM + k0 + ca0);
        *reinterpret_cast<uint4*>(&sAhi[ra1][ca1]) =
            *reinterpret_cast<const uint4*>(g_Ahi + (m0 + ra1) * K_DIM + k0 + ca1);
        *reinterpret_cast<uint4*>(&sAlo[ra0][ca0]) =
            *reinterpret_cast<const uint4*>(g_Alo + (m0 + ra0) * K_DIM + k0 + ca0);
        *reinterpret_cast<uint4*>(&sAlo[ra1][ca1]) =
            *reinterpret_cast<const uint4*>(g_Alo + (m0 + ra1) * K_DIM + k0 + ca1);
        // ---- load B tile (32x128) hi/lo ----
        *reinterpret_cast<uint4*>(&sBhi[kb0][nb0]) =
            *reinterpret_cast<const uint4*>(g_Whi + (size_t)(k0 + kb0) * O_DIM + n0 + nb0);
        *reinterpret_cast<uint4*>(&sBhi[kb1][nb1]) =
            *reinterpret_cast<const uint4*>(g_Whi + (size_t)(k0 + kb1) * O_DIM + n0 + nb1);
        *reinterpret_cast<uint4*>(&sBlo[kb0][nb0]) =
            *reinterpret_cast<const uint4*>(g_Wlo + (size_t)(k0 + kb0) * O_DIM + n0 + nb0);
        *reinterpret_cast<uint4*>(&sBlo[kb1][nb1]) =
            *reinterpret_cast<const uint4*>(g_Wlo + (size_t)(k0 + kb1) * O_DIM + n0 + nb1);

        __syncthreads();

#pragma unroll
        for (int ks = 0; ks < BK; ks += 16) {
            uint32_t ah[4][4], al[4][4], bh[4][2], bl[4][2];
#pragma unroll
            for (int mt = 0; mt < 4; mt++) {
                int row = warp_m * 64 + mt * 16 + lrow;
                int col = ks + lc8;
                ldsm_x4(ah[mt], smem_u32(&sAhi[row][col]));
                ldsm_x4(al[mt], smem_u32(&sAlo[row][col]));
            }
#pragma unroll
            for (int np = 0; np < 2; np++) {
                uint32_t t4[4];
                int krow = ks + lrow;
                int ncol = warp_n * 32 + np * 16 + lc8;
                ldsm_x4_t(t4, smem_u32(&sBhi[krow][ncol]));
                bh[np * 2][0] = t4[0]; bh[np * 2][1] = t4[1];
                bh[np * 2 + 1][0] = t4[2]; bh[np * 2 + 1][1] = t4[3];
                ldsm_x4_t(t4, smem_u32(&sBlo[krow][ncol]));
                bl[np * 2][0] = t4[0]; bl[np * 2][1] = t4[1];
                bl[np * 2 + 1][0] = t4[2]; bl[np * 2 + 1][1] = t4[3];
            }
#pragma unroll
            for (int mt = 0; mt < 4; mt++)
#pragma unroll
                for (int nt = 0; nt < 4; nt++) {
                    mma16816(acc[mt][nt], ah[mt], bh[nt]);  // Ah*Wh
                    mma16816(acc[mt][nt], ah[mt], bl[nt]);  // Ah*Wl
                    mma16816(acc[mt][nt], al[mt], bh[nt]);  // Al*Wh
                }
        }
        __syncthreads();
    }

    // ---- epilogue: + bias, write fp32 ----
    const int g   = lane >> 2;
    const int tig = lane & 3;
#pragma unroll
    for (int mt = 0; mt < 4; mt++) {
#pragma unroll
        for (int nt = 0; nt < 4; nt++) {
            int row = (int)m0 + warp_m * 64 + mt * 16 + g;
            int col = (int)n0 + warp_n * 32 + nt * 8 + tig * 2;
            float b0 = g_bias[col], b1 = g_bias[col + 1];
            float2 r0 = make_float2(acc[mt][nt][0] + b0, acc[mt][nt][1] + b1);
            float2 r1 = make_float2(acc[mt][nt][2] + b0, acc[mt][nt][3] + b1);
            *reinterpret_cast<float2*>(&out[(size_t)row * O_DIM + col]) = r0;
            *reinterpret_cast<float2*>(&out[(size_t)(row + 8) * O_DIM + col]) = r1;
        }
    }
}

// -------- launch --------
extern "C" void kernel_launch(void* const* d_in, const int* in_sizes, int n_in,
                              void* d_out, int out_size) {
    const float* x      = (const float*)d_in[0];
    const float* coeffs = (const float*)d_in[1];
    float* out          = (float*)d_out;

    vp_basis_kernel<<<(B_DIM * I_DIM + 255) / 256, 256>>>(x);
    vp_wprep_kernel<<<(I_DIM * O_DIM + 255) / 256, 256>>>(coeffs);
    vp_bias_kernel<<<O_DIM, 256>>>(coeffs);
    vp_gemm_kernel<<<dim3(O_DIM / BN, B_DIM / BM), 256>>>(out);
}

// round 9
// speedup vs baseline: 1.0065x; 1.0024x over previous
#include <cuda_runtime.h>
#include <cuda_bf16.h>
#include <cstdint>

// Problem dims
#define B_DIM 4096
#define I_DIM 1024
#define O_DIM 1024
#define NDEG  9            // d = 0..8 ; d=0 (V0=2) folded into bias
#define K_DIM (I_DIM * 8)  // 8192 : k = i*8 + (d-1)

// GEMM tiling
#define BM 128
#define BN 128
#define BK 32
#define SA_STRIDE 40   // bf16 elems, padded (128x32 A tile)
#define SB_STRIDE 136  // bf16 elems, padded (32x128 B tile)

// -------- device scratch (no runtime allocation allowed) --------
__device__ __align__(256) __nv_bfloat16 g_Ahi[(size_t)B_DIM * K_DIM];
__device__ __align__(256) __nv_bfloat16 g_Alo[(size_t)B_DIM * K_DIM];
__device__ __align__(256) __nv_bfloat16 g_Whi[(size_t)K_DIM * O_DIM];
__device__ __align__(256) __nv_bfloat16 g_Wlo[(size_t)K_DIM * O_DIM];
__device__ __align__(256) float         g_bias[O_DIM];

union Pack8 { uint4 u; __nv_bfloat16 h[8]; };

// -------- kernel 1: basis = Vieta-Pell(tanh(x)), split into bf16 hi/lo --------
__global__ void vp_basis_kernel(const float* __restrict__ x) {
    int idx = blockIdx.x * blockDim.x + threadIdx.x;  // b*I + i
    if (idx >= B_DIM * I_DIM) return;
    float t = tanhf(x[idx]);
    float v[NDEG];
    v[0] = 2.0f; v[1] = t;
#pragma unroll
    for (int d = 2; d < NDEG; d++) v[d] = t * v[d - 1] + v[d - 2];

    Pack8 hi, lo;
#pragma unroll
    for (int d = 1; d < NDEG; d++) {
        float f = v[d];
        __nv_bfloat16 h = __float2bfloat16(f);
        hi.h[d - 1] = h;
        lo.h[d - 1] = __float2bfloat16(f - __bfloat162float(h));
    }
    size_t base = (size_t)(idx >> 10) * K_DIM + (size_t)(idx & 1023) * 8;
    *reinterpret_cast<uint4*>(g_Ahi + base) = hi.u;
    *reinterpret_cast<uint4*>(g_Alo + base) = lo.u;
}

// -------- kernel 2: W[k=i*8+(d-1)][o] = coeffs[i][o][d], bf16 hi/lo --------
__global__ void vp_wprep_kernel(const float* __restrict__ coeffs) {
    int idx = blockIdx.x * blockDim.x + threadIdx.x;  // i*O + o
    if (idx >= I_DIM * O_DIM) return;
    int i = idx >> 10, o = idx & 1023;
    const float* src = coeffs + (size_t)idx * NDEG;
#pragma unroll
    for (int d = 1; d < NDEG; d++) {
        float f = src[d];
        __nv_bfloat16 h = __float2bfloat16(f);
        size_t w = (size_t)(i * 8 + d - 1) * O_DIM + o;
        g_Whi[w] = h;
        g_Wlo[w] = __float2bfloat16(f - __bfloat162float(h));
    }
}

// -------- kernel 3: bias[o] = 2 * sum_i coeffs[i][o][0] --------
__global__ void vp_bias_kernel(const float* __restrict__ coeffs) {
    __shared__ float red[256];
    int o = blockIdx.x;
    int t = threadIdx.x;
    float s = 0.0f;
#pragma unroll
    for (int j = 0; j < I_DIM / 256; j++) {
        int i = t + j * 256;
        s += coeffs[((size_t)i * O_DIM + o) * NDEG];
    }
    red[t] = s;
    __syncthreads();
    for (int off = 128; off > 0; off >>= 1) {
        if (t < off) red[t] += red[t + off];
        __syncthreads();
    }
    if (t == 0) g_bias[o] = 2.0f * red[0];
}

// -------- mma / ldmatrix helpers --------
__device__ __forceinline__ uint32_t smem_u32(const void* p) {
    return (uint32_t)__cvta_generic_to_shared(p);
}
__device__ __forceinline__ void ldsm_x4(uint32_t* r, uint32_t addr) {
    asm volatile("ldmatrix.sync.aligned.m8n8.x4.shared.b16 {%0,%1,%2,%3}, [%4];"
                 : "=r"(r[0]), "=r"(r[1]), "=r"(r[2]), "=r"(r[3]) : "r"(addr));
}
__device__ __forceinline__ void ldsm_x4_t(uint32_t* r, uint32_t addr) {
    asm volatile("ldmatrix.sync.aligned.m8n8.x4.trans.shared.b16 {%0,%1,%2,%3}, [%4];"
                 : "=r"(r[0]), "=r"(r[1]), "=r"(r[2]), "=r"(r[3]) : "r"(addr));
}
__device__ __forceinline__ void mma16816(float* c, const uint32_t* a, const uint32_t* b) {
    asm volatile(
        "mma.sync.aligned.m16n8k16.row.col.f32.bf16.bf16.f32 "
        "{%0,%1,%2,%3}, {%4,%5,%6,%7}, {%8,%9}, {%0,%1,%2,%3};"
        : "+f"(c[0]), "+f"(c[1]), "+f"(c[2]), "+f"(c[3])
        : "r"(a[0]), "r"(a[1]), "r"(a[2]), "r"(a[3]), "r"(b[0]), "r"(b[1]));
}

// -------- kernel 4: split-bf16 GEMM  out[b][o] = A @ W + bias --------
__global__ __launch_bounds__(256, 1)
void vp_gemm_kernel(float* __restrict__ out) {
    __shared__ __nv_bfloat16 sAhi[BM][SA_STRIDE];
    __shared__ __nv_bfloat16 sAlo[BM][SA_STRIDE];
    __shared__ __nv_bfloat16 sBhi[BK][SB_STRIDE];
    __shared__ __nv_bfloat16 sBlo[BK][SB_STRIDE];

    const int tid  = threadIdx.x;
    const int lane = tid & 31;
    const int wid  = tid >> 5;
    const int warp_m = wid & 1;   // 2 warps along M (64 rows each)
    const int warp_n = wid >> 1;  // 4 warps along N (32 cols each)
    const size_t m0 = (size_t)blockIdx.y * BM;
    const size_t n0 = (size_t)blockIdx.x * BN;

    float acc[4][4][4];
#pragma unroll
    for (int a = 0; a < 4; a++)
#pragma unroll
        for (int b = 0; b < 4; b++)
#pragma unroll
            for (int c = 0; c < 4; c++) acc[a][b][c] = 0.0f;

    // global->smem load coordinates (each thread: 2 x uint4 per matrix)
    const int ra0 = tid >> 2,          ca0 = (tid & 3) * 8;
    const int ra1 = (tid + 256) >> 2,  ca1 = (tid & 3) * 8;     // (tid+256)&3 == tid&3
    const int kb0 = tid >> 4,          nb0 = (tid & 15) * 8;
    const int kb1 = (tid + 256) >> 4,  nb1 = (tid & 15) * 8;

    // ldmatrix lane coordinates
    const int lrow = lane & 15;
    const int lc8  = (lane >> 4) * 8;

    for (int k0 = 0; k0 < K_DIM; k0 += BK) {
        // ---- load A tile (128x32) hi/lo ----
        *reinterpret_cast<uint4*>(&sAhi[ra0][ca0]) =
            *reinterpret_cast<const uint4*>(g_Ahi + (m0 + ra0) * K_DIM + k0 + ca0);
        *reinterpret_cast<uint4*>(&sAhi[ra1][ca1]) =
            *reinterpret_cast<const uint4*>(g_Ahi + (m0 + ra1) * K_DIM + k0 + ca1);
        *reinterpret_cast<uint4*>(&sAlo[ra0][ca0]) =
            *reinterpret_cast<const uint4*>(g_Alo + (m0 + ra0) * K_DIM + k0 + ca0);
        *reinterpret_cast<uint4*>(&sAlo[ra1][ca1]) =
            *reinterpret_cast<const uint4*>(g_Alo + (m0 + ra1) * K_DIM + k0 + ca1);
        // ---- load B tile (32x128) hi/lo ----
        *reinterpret_cast<uint4*>(&sBhi[kb0][nb0]) =
            *reinterpret_cast<const uint4*>(g_Whi + (size_t)(k0 + kb0) * O_DIM + n0 + nb0);
        *reinterpret_cast<uint4*>(&sBhi[kb1][nb1]) =
            *reinterpret_cast<const uint4*>(g_Whi + (size_t)(k0 + kb1) * O_DIM + n0 + nb1);
        *reinterpret_cast<uint4*>(&sBlo[kb0][nb0]) =
            *reinterpret_cast<const uint4*>(g_Wlo + (size_t)(k0 + kb0) * O_DIM + n0 + nb0);
        *reinterpret_cast<uint4*>(&sBlo[kb1][nb1]) =
            *reinterpret_cast<const uint4*>(g_Wlo + (size_t)(k0 + kb1) * O_DIM + n0 + nb1);

        __syncthreads();

#pragma unroll
        for (int ks = 0; ks < BK; ks += 16) {
            uint32_t ah[4][4], al[4][4], bh[4][2], bl[4][2];
#pragma unroll
            for (int mt = 0; mt < 4; mt++) {
                int row = warp_m * 64 + mt * 16 + lrow;
                int col = ks + lc8;
                ldsm_x4(ah[mt], smem_u32(&sAhi[row][col]));
                ldsm_x4(al[mt], smem_u32(&sAlo[row][col]));
            }
#pragma unroll
            for (int np = 0; np < 2; np++) {
                uint32_t t4[4];
                int krow = ks + lrow;
                int ncol = warp_n * 32 + np * 16 + lc8;
                ldsm_x4_t(t4, smem_u32(&sBhi[krow][ncol]));
                bh[np * 2][0] = t4[0]; bh[np * 2][1] = t4[1];
                bh[np * 2 + 1][0] = t4[2]; bh[np * 2 + 1][1] = t4[3];
                ldsm_x4_t(t4, smem_u32(&sBlo[krow][ncol]));
                bl[np * 2][0] = t4[0]; bl[np * 2][1] = t4[1];
                bl[np * 2 + 1][0] = t4[2]; bl[np * 2 + 1][1] = t4[3];
            }
#pragma unroll
            for (int mt = 0; mt < 4; mt++)
#pragma unroll
                for (int nt = 0; nt < 4; nt++) {
                    mma16816(acc[mt][nt], ah[mt], bh[nt]);  // Ah*Wh
                    mma16816(acc[mt][nt], ah[mt], bl[nt]);  // Ah*Wl
                    mma16816(acc[mt][nt], al[mt], bh[nt]);  // Al*Wh
                }
        }
        __syncthreads();
    }

    // ---- epilogue: + bias, write fp32 ----
    const int g   = lane >> 2;
    const int tig = lane & 3;
#pragma unroll
    for (int mt = 0; mt < 4; mt++) {
#pragma unroll
        for (int nt = 0; nt < 4; nt++) {
            int row = (int)m0 + warp_m * 64 + mt * 16 + g;
            int col = (int)n0 + warp_n * 32 + nt * 8 + tig * 2;
            float b0 = g_bias[col], b1 = g_bias[col + 1];
            float2 r0 = make_float2(acc[mt][nt][0] + b0, acc[mt][nt][1] + b1);
            float2 r1 = make_float2(acc[mt][nt][2] + b0, acc[mt][nt][3] + b1);
            *reinterpret_cast<float2*>(&out[(size_t)row * O_DIM + col]) = r0;
            *reinterpret_cast<float2*>(&out[(size_t)(row + 8) * O_DIM + col]) = r1;
        }
    }
}

// -------- launch --------
extern "C" void kernel_launch(void* const* d_in, const int* in_sizes, int n_in,
                              void* d_out, int out_size) {
    const float* x      = (const float*)d_in[0];
    const float* coeffs = (const float*)d_in[1];
    float* out          = (float*)d_out;

    vp_basis_kernel<<<(B_DIM * I_DIM + 255) / 256, 256>>>(x);
    vp_wprep_kernel<<<(I_DIM * O_DIM + 255) / 256, 256>>>(coeffs);
    vp_bias_kernel<<<O_DIM, 256>>>(coeffs);
    vp_gemm_kernel<<<dim3(O_DIM / BN, B_DIM / BM), 256>>>(out);
}